// round 1
// baseline (speedup 1.0000x reference)
#include <cuda_runtime.h>

// FwFM forward on GB300.
// out[s] = bias + sum_f linear[idx[s][f]] + sum_{i<j} fw[p] * <E[idx[s][i]], E[idx[s][j]]>
//
// Layout: 8 lanes per sample (each lane owns 2 of the 16 dims as a packed f32x2),
// 4 samples per warp, 4 warps per block -> 16 samples/block, 512 blocks.
// Second order uses the factored form: for each i, t_i = sum_{j>i} w_p * x_j,
// acc += x_i * t_i  (741 + 39 FMAs per dim instead of 741 MUL+FMA pairs),
// executed with packed fma.rn.f32x2 so one instruction covers 2 dims.
// Pair weights are staged in smem pre-splatted as {w,w} so a single broadcast
// LDS.64 feeds the packed FMA directly.

#define FIELDS 39
#define EDIM 16
#define CROSS 741            // 39*38/2
#define BATCH 8192
#define SAMPLES_PER_WARP 4
#define WARPS_PER_BLOCK 4
#define SAMPLES_PER_BLOCK (SAMPLES_PER_WARP * WARPS_PER_BLOCK)
#define THREADS (32 * WARPS_PER_BLOCK)

typedef unsigned long long ull;

__global__ __launch_bounds__(THREADS, 4)
void fwfm_kernel(const int* __restrict__ inputs,
                 const float* __restrict__ emb,
                 const float* __restrict__ fw,
                 const float* __restrict__ lw,
                 const float* __restrict__ bias,
                 float* __restrict__ out)
{
    __shared__ ull w2[CROSS];                         // {w,w} splatted pair weights
    __shared__ int idx_sh[SAMPLES_PER_BLOCK * FIELDS];

    const int tid = threadIdx.x;

    // Stage pair weights, pre-splatted into both halves of a 64-bit word.
    for (int p = tid; p < CROSS; p += THREADS) {
        float w = fw[p];
        ull v;
        asm("mov.b64 %0, {%1, %2};" : "=l"(v) : "f"(w), "f"(w));
        w2[p] = v;
    }
    // Stage this block's indices (coalesced).
    const int base = blockIdx.x * SAMPLES_PER_BLOCK * FIELDS;
    for (int k = tid; k < SAMPLES_PER_BLOCK * FIELDS; k += THREADS)
        idx_sh[k] = inputs[base + k];
    __syncthreads();

    const int warp = tid >> 5;
    const int lane = tid & 31;
    const int sub  = lane >> 3;       // sample within warp (0..3)
    const int d    = lane & 7;        // dim-pair index (dims 2d, 2d+1)
    const int s_local = warp * SAMPLES_PER_WARP + sub;
    const int sample  = blockIdx.x * SAMPLES_PER_BLOCK + s_local;
    const int* my_idx = &idx_sh[s_local * FIELDS];

    // Gather embeddings: lane d loads dims [2d, 2d+1] of each of 39 fields.
    // 8 lanes of a sample cover one contiguous 64B row -> one L2 line per field.
    ull x[FIELDS];
#pragma unroll
    for (int f = 0; f < FIELDS; f++) {
        const int g = my_idx[f];
        x[f] = *reinterpret_cast<const ull*>(emb + (size_t)g * EDIM + 2 * d);
    }

    // First-order partial: lane d covers fields f == d (mod 8).
    float lin = 0.f;
    for (int f = d; f < FIELDS; f += 8)
        lin += lw[my_idx[f]];

    // Second order with packed f32x2 FMAs.
    ull acc;
    asm("mov.b64 %0, {%1, %2};" : "=l"(acc) : "f"(0.f), "f"(0.f));
    int p = 0;
#pragma unroll
    for (int i = 0; i < FIELDS - 1; i++) {
        ull t;
        asm("mul.rn.f32x2 %0, %1, %2;" : "=l"(t) : "l"(w2[p]), "l"(x[i + 1]));
        p++;
#pragma unroll
        for (int j = i + 2; j < FIELDS; j++) {
            asm("fma.rn.f32x2 %0, %1, %2, %3;"
                : "=l"(t) : "l"(w2[p]), "l"(x[j]), "l"(t));
            p++;
        }
        asm("fma.rn.f32x2 %0, %1, %2, %3;"
            : "=l"(acc) : "l"(x[i]), "l"(t), "l"(acc));
    }

    float lo, hi;
    asm("mov.b64 {%0, %1}, %2;" : "=f"(lo), "=f"(hi) : "l"(acc));
    float v = lo + hi + lin;

    // Reduce across the 8 lanes of this sample (xor 4,2,1 stays in-group).
    v += __shfl_xor_sync(0xffffffffu, v, 4);
    v += __shfl_xor_sync(0xffffffffu, v, 2);
    v += __shfl_xor_sync(0xffffffffu, v, 1);

    if (d == 0)
        out[sample] = v + bias[0];
}

extern "C" void kernel_launch(void* const* d_in, const int* in_sizes, int n_in,
                              void* d_out, int out_size)
{
    const int*   inputs = (const int*)d_in[0];
    const float* emb    = (const float*)d_in[1];
    const float* fw     = (const float*)d_in[2];
    const float* lw     = (const float*)d_in[3];
    const float* bias   = (const float*)d_in[4];
    float*       out    = (float*)d_out;

    fwfm_kernel<<<BATCH / SAMPLES_PER_BLOCK, THREADS>>>(inputs, emb, fw, lw, bias, out);
}

// round 2
// speedup vs baseline: 1.1056x; 1.1056x over previous
#include <cuda_runtime.h>

// FwFM forward on GB300 — R2: break FMA dependency chains with 4 independent
// packed accumulators per i-row (ILP 4 on the fma pipe).
//
// Layout: 8 lanes per sample (each lane owns dims 2d,2d+1 as packed f32x2),
// 4 samples/warp, 4 warps/block -> 16 samples/block, 512 blocks.

#define FIELDS 39
#define EDIM 16
#define CROSS 741            // 39*38/2
#define BATCH 8192
#define SAMPLES_PER_WARP 4
#define WARPS_PER_BLOCK 4
#define SAMPLES_PER_BLOCK (SAMPLES_PER_WARP * WARPS_PER_BLOCK)
#define THREADS (32 * WARPS_PER_BLOCK)

typedef unsigned long long ull;

__device__ __forceinline__ ull pk_zero() {
    ull v;
    asm("mov.b64 %0, {%1, %1};" : "=l"(v) : "f"(0.0f));
    return v;
}
__device__ __forceinline__ ull pk_fma(ull a, ull b, ull c) {
    ull r;
    asm("fma.rn.f32x2 %0, %1, %2, %3;" : "=l"(r) : "l"(a), "l"(b), "l"(c));
    return r;
}
__device__ __forceinline__ ull pk_add(ull a, ull b) {
    ull r;
    asm("add.rn.f32x2 %0, %1, %2;" : "=l"(r) : "l"(a), "l"(b));
    return r;
}

__global__ __launch_bounds__(THREADS, 4)
void fwfm_kernel(const int* __restrict__ inputs,
                 const float* __restrict__ emb,
                 const float* __restrict__ fw,
                 const float* __restrict__ lw,
                 const float* __restrict__ bias,
                 float* __restrict__ out)
{
    __shared__ ull w2[CROSS];                         // {w,w} splatted pair weights
    __shared__ int idx_sh[SAMPLES_PER_BLOCK * FIELDS];

    const int tid = threadIdx.x;

    // Stage pair weights, pre-splatted into both halves of a 64-bit word.
    for (int p = tid; p < CROSS; p += THREADS) {
        float w = fw[p];
        ull v;
        asm("mov.b64 %0, {%1, %1};" : "=l"(v) : "f"(w));
        w2[p] = v;
    }
    // Stage this block's indices (coalesced).
    const int base = blockIdx.x * SAMPLES_PER_BLOCK * FIELDS;
    for (int k = tid; k < SAMPLES_PER_BLOCK * FIELDS; k += THREADS)
        idx_sh[k] = inputs[base + k];
    __syncthreads();

    const int warp = tid >> 5;
    const int lane = tid & 31;
    const int sub  = lane >> 3;       // sample within warp (0..3)
    const int d    = lane & 7;        // dim-pair index (dims 2d, 2d+1)
    const int s_local = warp * SAMPLES_PER_WARP + sub;
    const int sample  = blockIdx.x * SAMPLES_PER_BLOCK + s_local;
    const int* my_idx = &idx_sh[s_local * FIELDS];

    // Gather embeddings: lane d loads dims [2d, 2d+1] of each of 39 fields.
    // 8 lanes of a sample cover one contiguous 64B row. 39 independent LDG.64
    // issued up front -> high MLP.
    ull x[FIELDS];
#pragma unroll
    for (int f = 0; f < FIELDS; f++) {
        const int g = my_idx[f];
        x[f] = *reinterpret_cast<const ull*>(emb + (size_t)g * EDIM + 2 * d);
    }

    // First-order partial: lane d covers fields f == d (mod 8).
    float lin = 0.f;
#pragma unroll
    for (int f = d; f < FIELDS; f += 8)
        lin += lw[my_idx[f]];

    // Second order: for each i, t_i = sum_{j>i} w_p * x_j ; acc += x_i * t_i.
    // Inner sum split into 4 independent packed accumulators to break the
    // serial FMA chain (chain depth per row ~10 instead of ~38).
    ull acc = pk_zero();
    int p = 0;
#pragma unroll
    for (int i = 0; i < FIELDS - 1; i++) {
        ull t0 = pk_zero(), t1 = pk_zero(), t2 = pk_zero(), t3 = pk_zero();
        int k = 0;
#pragma unroll
        for (int j = i + 1; j < FIELDS; j++, k++) {
            const ull wx = w2[p + k];
            switch (k & 3) {
                case 0: t0 = pk_fma(wx, x[j], t0); break;
                case 1: t1 = pk_fma(wx, x[j], t1); break;
                case 2: t2 = pk_fma(wx, x[j], t2); break;
                default: t3 = pk_fma(wx, x[j], t3); break;
            }
        }
        p += k;
        const ull ts = pk_add(pk_add(t0, t1), pk_add(t2, t3));
        acc = pk_fma(x[i], ts, acc);
    }

    float lo, hi;
    asm("mov.b64 {%0, %1}, %2;" : "=f"(lo), "=f"(hi) : "l"(acc));
    float v = lo + hi + lin;

    // Reduce across the 8 lanes of this sample (xor 4,2,1 stays in-group).
    v += __shfl_xor_sync(0xffffffffu, v, 4);
    v += __shfl_xor_sync(0xffffffffu, v, 2);
    v += __shfl_xor_sync(0xffffffffu, v, 1);

    if (d == 0)
        out[sample] = v + bias[0];
}

extern "C" void kernel_launch(void* const* d_in, const int* in_sizes, int n_in,
                              void* d_out, int out_size)
{
    const int*   inputs = (const int*)d_in[0];
    const float* emb    = (const float*)d_in[1];
    const float* fw     = (const float*)d_in[2];
    const float* lw     = (const float*)d_in[3];
    const float* bias   = (const float*)d_in[4];
    float*       out    = (float*)d_out;

    fwfm_kernel<<<BATCH / SAMPLES_PER_BLOCK, THREADS>>>(inputs, emb, fw, lw, bias, out);
}